// round 15
// baseline (speedup 1.0000x reference)
#include <cuda_runtime.h>
#include <cuda_fp16.h>
#include <stdint.h>
#include <math.h>

#define BB 2
#define SS 2048
#define EE 1024
#define HH 16
#define DD 64
#define MTOT (BB*SS)

// ---------------------------------------------------------------------------
// Scratch (device globals — no allocation allowed)
// ---------------------------------------------------------------------------
__device__ float g_bias8[HH*SS];                       // bias*8*log2e
__device__ __half g_ahi[MTOT*EE];                      // hs fp16
__device__ __half g_wthi[4u*EE*EE];                    // W^T fp16 (q,k,v,o)
__device__ __half g_chi[MTOT*EE];                      // ctx fp16
__device__ __half g_qhi[BB*HH*SS*DD];                  // [b][h][s][d]
__device__ __half g_khi[BB*HH*SS*DD];                  // [b][h][s][d]
__device__ __half g_vthi[BB*HH*SS*DD];                 // [b][h][d][s]

// scheduling state
__device__ unsigned int g_ctr;
__device__ unsigned int g_flagQ[32*16];    // [mblk][h]
__device__ unsigned int g_cntK[16], g_cntV[16];
__device__ unsigned int g_flagCtx[32*16];  // [mblk][h]

#define NQKV 1536
#define NATT 512
#define NOUT 512
#define NTOT (NQKV + NATT + NOUT)

// ---------------------------------------------------------------------------
// helpers
// ---------------------------------------------------------------------------
__device__ __forceinline__ uint32_t smem_u32(const void* p) {
    uint32_t r;
    asm("{ .reg .u64 t; cvta.to.shared.u64 t, %1; cvt.u32.u64 %0, t; }"
        : "=r"(r) : "l"(p));
    return r;
}

__device__ __forceinline__ void cp16(uint32_t dst, const void* src) {
    asm volatile("cp.async.cg.shared.global [%0], [%1], 16;"
                 :: "r"(dst), "l"(__cvta_generic_to_global(src)) : "memory");
}

__device__ __forceinline__ void mma_f16(float* c, const uint32_t* a, const uint32_t* b) {
    asm volatile(
        "mma.sync.aligned.m16n8k16.row.col.f32.f16.f16.f32 "
        "{%0,%1,%2,%3}, {%4,%5,%6,%7}, {%8,%9}, {%0,%1,%2,%3};"
        : "+f"(c[0]), "+f"(c[1]), "+f"(c[2]), "+f"(c[3])
        : "r"(a[0]), "r"(a[1]), "r"(a[2]), "r"(a[3]), "r"(b[0]), "r"(b[1]));
}

__device__ __forceinline__ void ldsm_x4(uint32_t* r, uint32_t addr) {
    asm volatile("ldmatrix.sync.aligned.m8n8.x4.shared.b16 {%0,%1,%2,%3}, [%4];"
        : "=r"(r[0]), "=r"(r[1]), "=r"(r[2]), "=r"(r[3]) : "r"(addr));
}

__device__ __forceinline__ uint32_t pack_f16x2(float a, float b) {
    uint32_t d;
    asm("cvt.rn.f16x2.f32 %0, %1, %2;" : "=r"(d) : "f"(b), "f"(a));
    return d;
}

__device__ __forceinline__ void wait_flag(unsigned int* f, unsigned int want) {
    if (threadIdx.x == 0) {
        while (atomicAdd(f, 0u) < want) __nanosleep(64);
        __threadfence();
    }
    __syncthreads();
}

// ---------------------------------------------------------------------------
// prep kernel: weight transpose + hs convert + bias table + flag zeroing
// ---------------------------------------------------------------------------
__global__ void prep_kernel(const float* __restrict__ hs,
                            const float* __restrict__ Wq, const float* __restrict__ Wk,
                            const float* __restrict__ Wv, const float* __restrict__ Wo,
                            const float* __restrict__ rel_bias) {
    int bx = blockIdx.x, tid = threadIdx.x;
    if (bx < 4096) {
        __shared__ float t[32][33];
        int widx = bx >> 10, tile = bx & 1023;
        const float* W = (widx == 0) ? Wq : (widx == 1) ? Wk : (widx == 2) ? Wv : Wo;
        int n0 = (tile & 31) * 32, k0 = (tile >> 5) * 32;
        int tx = tid & 31, ty = tid >> 5;
#pragma unroll
        for (int i = 0; i < 4; i++)
            t[ty + i * 8][tx] = W[(size_t)(k0 + ty + i * 8) * EE + n0 + tx];
        __syncthreads();
        __half* hi = g_wthi + (size_t)widx * EE * EE;
#pragma unroll
        for (int i = 0; i < 4; i++) {
            int n = n0 + ty + i * 8, k = k0 + tx;
            hi[(size_t)n * EE + k] = __float2half(t[tx][ty + i * 8]);
        }
    } else if (bx < 8192) {
        int i = (bx - 4096) * 256 + tid;
        float4 v = ((const float4*)hs)[i];
        ((uint32_t*)g_ahi)[i * 2]     = pack_f16x2(v.x, v.y);
        ((uint32_t*)g_ahi)[i * 2 + 1] = pack_f16x2(v.z, v.w);
    } else if (bx < 8320) {
        int idx = (bx - 8192) * 256 + tid;
        int h = idx / SS, d = idx % SS;
        int bucket;
        if (d < 16) bucket = d;
        else {
            float t2 = (logf((float)d * 0.0625f) / 1.3862943611198906f) * 16.0f;
            int lb = 16 + (int)t2;
            bucket = lb < 31 ? lb : 31;
        }
        g_bias8[idx] = rel_bias[bucket * HH + h] * (8.0f * 1.4426950408889634f);
    } else {
        if (tid == 0) g_ctr = 0;
        if (tid < 512) { g_flagQ[tid] = 0; g_flagCtx[tid] = 0; }
        if (tid < 16) { g_cntK[tid] = 0; g_cntV[tid] = 0; }
    }
}

// ---------------------------------------------------------------------------
// GEMM tile body (BM=128, BN=64, BK=32, 4-stage, 8 warps 4m x 2n)
//   ctx_gate != 0: per-head progressive wait on g_flagCtx[mblk][git>>1]
// ---------------------------------------------------------------------------
#define RPAD 80
#define ATILE (128 * RPAD)
#define BTILE (64 * RPAD)
#define STAGE_BYTES (ATILE + BTILE)
#define NITER 32

__device__ __forceinline__ void gemm_tile(char* sm, const __half* A, const __half* Bw,
                                          const float* bias, float* outp,
                                          int mblk, int nblk, int widx, int ctx_gate) {
    int tid = threadIdx.x;
    int lane = tid & 31, wid = tid >> 5;
    int wm = wid & 3, wn = wid >> 2;
    int g = lane >> 2, tg = lane & 3;
    int m0 = mblk * 128, n0 = nblk * 64;

    float c[2][4][4];
#pragma unroll
    for (int mt = 0; mt < 2; mt++)
#pragma unroll
        for (int nt = 0; nt < 4; nt++)
#pragma unroll
            for (int i = 0; i < 4; i++) c[mt][nt][i] = 0.f;

    uint32_t smbase = smem_u32(sm);
    uint32_t a_lrow = ((uint32_t)((lane >> 3) & 1)) * 8 + (lane & 7);
    uint32_t a_lcol = ((uint32_t)(lane >> 4)) * 16;
    uint32_t b_lrow = lane & 7;
    uint32_t b_lcol = ((uint32_t)(lane >> 3)) * 16;

    auto gate = [&](int git) {
        if (ctx_gate) wait_flag(&g_flagCtx[mblk * 16 + (git >> 1)], 1u);
    };

    auto load_stage = [&](int git, int s) {
        int kb = git * 32;
        uint32_t st = smbase + s * STAGE_BYTES;
#pragma unroll
        for (int i = 0; i < 2; i++) {
            int ch = tid + i * 256;
            int m = ch >> 2, lk = ch & 3;
            cp16(st + m * RPAD + lk * 16, A + (size_t)(m0 + m) * EE + kb + lk * 8);
        }
        {
            int mb = tid >> 2, lkb = tid & 3;
            cp16(st + ATILE + mb * RPAD + lkb * 16,
                 Bw + (size_t)(n0 + mb) * EE + kb + lkb * 8);
        }
    };

#pragma unroll
    for (int p = 0; p < 3; p++) {
        gate(p);
        load_stage(p, p);
        asm volatile("cp.async.commit_group;" ::: "memory");
    }

    for (int git = 0; git < NITER; git++) {
        asm volatile("cp.async.wait_group 2;" ::: "memory");
        __syncthreads();

        int nx = git + 3;
        if (nx < NITER) {
            gate(nx);
            load_stage(nx, nx & 3);
        }
        asm volatile("cp.async.commit_group;" ::: "memory");

        uint32_t st = smbase + (git & 3) * STAGE_BYTES;
        uint32_t Bs = st + ATILE;

        uint32_t b[4][4];
#pragma unroll
        for (int nt = 0; nt < 4; nt++)
            ldsm_x4(b[nt], Bs + (wn * 32 + nt * 8 + b_lrow) * RPAD + b_lcol);

        uint32_t a[2][8];
#pragma unroll
        for (int mt = 0; mt < 2; mt++)
#pragma unroll
            for (int ks = 0; ks < 2; ks++)
                ldsm_x4(&a[mt][ks * 4],
                        st + (wm * 32 + mt * 16 + a_lrow) * RPAD + ks * 32 + a_lcol);
#pragma unroll
        for (int ks = 0; ks < 2; ks++)
#pragma unroll
            for (int mt = 0; mt < 2; mt++)
#pragma unroll
                for (int nt = 0; nt < 4; nt++)
                    mma_f16(c[mt][nt], &a[mt][ks * 4], &b[nt][ks * 2]);
    }

    // epilogue
#pragma unroll
    for (int mt = 0; mt < 2; mt++) {
#pragma unroll
        for (int nt = 0; nt < 4; nt++) {
            int n = n0 + wn * 32 + nt * 8 + 2 * tg;
            float bx = bias[n], by = bias[n + 1];
#pragma unroll
            for (int hh = 0; hh < 2; hh++) {
                int r = m0 + wm * 32 + mt * 16 + g + hh * 8;
                float vx = c[mt][nt][2 * hh] + bx;
                float vy = c[mt][nt][2 * hh + 1] + by;
                if (widx == 3) {
                    *(float2*)(outp + (size_t)r * EE + n) = make_float2(vx, vy);
                } else {
                    uint32_t hp = pack_f16x2(vx, vy);
                    int head = n >> 6, d = n & 63;
                    int bidx = r >> 11, srow = r & 2047;
                    size_t bh = (size_t)bidx * HH + head;
                    if (widx == 2) {
                        size_t i0 = (bh * DD + d) * SS + srow;
                        size_t i1 = (bh * DD + d + 1) * SS + srow;
                        g_vthi[i0] = __ushort_as_half((unsigned short)(hp & 0xffff));
                        g_vthi[i1] = __ushort_as_half((unsigned short)(hp >> 16));
                    } else if (widx == 1) {
                        *(uint32_t*)(g_khi + (bh * SS + srow) * DD + d) = hp;
                    } else {
                        *(uint32_t*)(g_qhi + (bh * SS + srow) * DD + d) = hp;
                    }
                }
            }
        }
    }

    if (widx != 3) {
        __threadfence();
        __syncthreads();
        if (tid == 0) {
            if (widx == 0)      atomicExch(&g_flagQ[mblk * 16 + nblk], 1u);
            else if (widx == 1) atomicAdd(&g_cntK[nblk], 1u);
            else                atomicAdd(&g_cntV[nblk], 1u);
        }
    }
}

// ---------------------------------------------------------------------------
// attention tile body: fixed-max softmax (M=12, exp2 domain)
// ---------------------------------------------------------------------------
#define QT 128
#define KT 64
#define PITCH 144
#define KV_TILE (KT * PITCH)
#define KV_STAGE (2 * KV_TILE)
#define OFF_Q  8192
#define OFF_ST (OFF_Q + QT * PITCH)
#define MEGA_SMEM (OFF_ST + 3 * KV_STAGE)   // 81920

#define SCALE_L2E 0.18033688011112042f      // 0.125 * log2(e)
#define FIXMAX 12.0f

__device__ __forceinline__ void attn_tile(char* sm, int qt, int h, int b) {
    float* bias_s = (float*)sm;
    uint32_t smb = smem_u32(sm);
    int tid = threadIdx.x, lane = tid & 31, w = tid >> 5;
    int g = lane >> 2, tg = lane & 3;
    int q0 = qt * QT;
    size_t bh = (size_t)b * HH + h;
    int mblk = b * 16 + qt;

    // wait for producers
    if (tid == 0) {
        while (atomicAdd(&g_flagQ[mblk * 16 + h], 0u) == 0u) __nanosleep(64);
        while (atomicAdd(&g_cntK[h], 0u) < 32u) __nanosleep(64);
        while (atomicAdd(&g_cntV[h], 0u) < 32u) __nanosleep(64);
        __threadfence();
    }
    __syncthreads();

    const __half* Khi = g_khi + bh * SS * DD;
    const __half* Vhi = g_vthi + bh * DD * SS;
    const __half* Qhi = g_qhi + (bh * SS + q0) * DD;

    const float4* br = (const float4*)(g_bias8 + h * SS);
    for (int i = tid; i < SS / 4; i += 256) ((float4*)bias_s)[i] = br[i];

    auto load_kv = [&](int kt, int s) {
        uint32_t base = smb + OFF_ST + s * KV_STAGE;
        int k0 = kt * KT;
#pragma unroll
        for (int i = 0; i < 2; i++) {
            int ch = tid + i * 256;
            int r = ch >> 3, cc = ch & 7;
            uint32_t off = r * PITCH + cc * 16;
            cp16(base + off,           Khi + (size_t)(k0 + r) * 64 + cc * 8);
            cp16(base + KV_TILE + off, Vhi + (size_t)r * SS + k0 + cc * 8);
        }
    };

#pragma unroll
    for (int i = 0; i < 4; i++) {
        int ch = tid + i * 256;
        int r = ch >> 3, cc = ch & 7;
        cp16(smb + OFF_Q + r * PITCH + cc * 16, Qhi + r * 64 + cc * 8);
    }
    load_kv(0, 0);
    asm volatile("cp.async.commit_group;" ::: "memory");
    load_kv(1, 1);
    asm volatile("cp.async.commit_group;" ::: "memory");

    float l0 = 0.f, l1 = 0.f;
    float acc[8][4];
#pragma unroll
    for (int j = 0; j < 8; j++)
#pragma unroll
        for (int i = 0; i < 4; i++) acc[j][i] = 0.f;

    uint32_t qh[16];
    int qrow0 = q0 + w * 16 + g;
    int qrow1 = qrow0 + 8;

    uint32_t a_lrow = ((uint32_t)((lane >> 3) & 1)) * 8 + (lane & 7);
    uint32_t a_lcol = ((uint32_t)(lane >> 4)) * 16;
    uint32_t kv_off = (lane & 7) * PITCH + ((uint32_t)(lane >> 3)) * 16;

    for (int kt = 0; kt < 32; kt++) {
        asm volatile("cp.async.wait_group 1;" ::: "memory");
        __syncthreads();

        if (kt + 2 < 32) load_kv(kt + 2, (kt + 2) % 3);
        asm volatile("cp.async.commit_group;" ::: "memory");

        if (kt == 0) {
#pragma unroll
            for (int s = 0; s < 4; s++)
                ldsm_x4(&qh[4 * s],
                        smb + OFF_Q + (w * 16 + a_lrow) * PITCH + s * 32 + a_lcol);
        }

        uint32_t stg = smb + OFF_ST + (kt % 3) * KV_STAGE;

        // ---- S = Q K^T ----
        float sc[8][4];
#pragma unroll
        for (int j = 0; j < 8; j++) {
#pragma unroll
            for (int i = 0; i < 4; i++) sc[j][i] = 0.f;
            uint32_t kbase = stg + j * (8 * PITCH) + kv_off;
            uint32_t kh[8];
            ldsm_x4(&kh[0], kbase);
            ldsm_x4(&kh[4], kbase + 64);
#pragma unroll
            for (int s = 0; s < 4; s++)
                mma_f16(sc[j], &qh[4 * s], &kh[2 * s]);
        }

        // ---- p = exp2(scale*S + bias - FIXMAX); accumulate l ----
        int colb = kt * KT + 2 * tg;
#pragma unroll
        for (int j = 0; j < 8; j++) {
            int col = colb + 8 * j;
            int d0 = qrow0 - col, d1 = qrow1 - col;
            sc[j][0] = exp2f(sc[j][0] * SCALE_L2E + (bias_s[max(d0, 0)] - FIXMAX));
            sc[j][1] = exp2f(sc[j][1] * SCALE_L2E + (bias_s[max(d0 - 1, 0)] - FIXMAX));
            sc[j][2] = exp2f(sc[j][2] * SCALE_L2E + (bias_s[max(d1, 0)] - FIXMAX));
            sc[j][3] = exp2f(sc[j][3] * SCALE_L2E + (bias_s[max(d1 - 1, 0)] - FIXMAX));
            l0 += sc[j][0] + sc[j][1];
            l1 += sc[j][2] + sc[j][3];
        }

        // ---- P -> fp16 fragments ----
        uint32_t ph[8], ph2[8];
#pragma unroll
        for (int j = 0; j < 8; j++) {
            ph[j]  = pack_f16x2(sc[j][0], sc[j][1]);
            ph2[j] = pack_f16x2(sc[j][2], sc[j][3]);
        }

        // ---- O += P V ----
#pragma unroll
        for (int j = 0; j < 8; j++) {
            uint32_t vbase = stg + KV_TILE + j * (8 * PITCH) + kv_off;
            uint32_t vh[8];
            ldsm_x4(&vh[0], vbase);
            ldsm_x4(&vh[4], vbase + 64);
#pragma unroll
            for (int s = 0; s < 4; s++) {
                uint32_t pA[4] = { ph[2*s], ph2[2*s], ph[2*s+1], ph2[2*s+1] };
                mma_f16(acc[j], pA, &vh[2 * s]);
            }
        }
    }

    // ---- final l reduction ----
    l0 += __shfl_xor_sync(0xffffffffu, l0, 1);
    l0 += __shfl_xor_sync(0xffffffffu, l0, 2);
    l1 += __shfl_xor_sync(0xffffffffu, l1, 1);
    l1 += __shfl_xor_sync(0xffffffffu, l1, 2);

    float inv0 = 1.f / l0, inv1 = 1.f / l1;
#pragma unroll
    for (int j = 0; j < 8; j++) {
        int e = h * 64 + 8 * j + 2 * tg;
        {
            float ox = acc[j][0] * inv0, oy = acc[j][1] * inv0;
            size_t base = ((size_t)b * SS + qrow0) * EE + e;
            *(uint32_t*)(g_chi + base) = pack_f16x2(ox, oy);
        }
        {
            float ox = acc[j][2] * inv1, oy = acc[j][3] * inv1;
            size_t base = ((size_t)b * SS + qrow1) * EE + e;
            *(uint32_t*)(g_chi + base) = pack_f16x2(ox, oy);
        }
    }

    __threadfence();
    __syncthreads();
    if (tid == 0) atomicExch(&g_flagCtx[mblk * 16 + h], 1u);
}

// ---------------------------------------------------------------------------
// mega kernel: persistent CTAs, dynamic tile claiming
//   tiles [0,1536): QKV gemm (head-major)
//   tiles [1536,2048): attention, h-OUTER (h = t2>>5, bqt = t2&31)
//   tiles [2048,2560): O-proj, progressive per-head ctx gating
// ---------------------------------------------------------------------------
__global__ __launch_bounds__(256, 2)
void mega(const float* __restrict__ bq, const float* __restrict__ bk,
          const float* __restrict__ bv, const float* __restrict__ bo,
          float* __restrict__ outp) {
    extern __shared__ char sm[];
    __shared__ unsigned int s_t;

    for (;;) {
        if (threadIdx.x == 0) s_t = atomicAdd(&g_ctr, 1u);
        __syncthreads();
        unsigned int t = s_t;
        if (t >= NTOT) return;

        if (t < NQKV) {
            int h = t / 96, r = t % 96;
            int widx = r >> 5, mblk = r & 31;
            const float* bias = (widx == 0) ? bq : (widx == 1) ? bk : bv;
            gemm_tile(sm, g_ahi, g_wthi + (size_t)widx * EE * EE,
                      bias, nullptr, mblk, h, widx, 0);
        } else if (t < NQKV + NATT) {
            int t2 = t - NQKV;
            int h = t2 >> 5, bqt = t2 & 31;
            attn_tile(sm, bqt & 15, h, bqt >> 4);
        } else {
            int t3 = t - NQKV - NATT;
            int mblk = t3 >> 4, nblk = t3 & 15;
            gemm_tile(sm, g_chi, g_wthi + (size_t)3 * EE * EE, bo, outp,
                      mblk, nblk, 3, 1);
        }
        __syncthreads();
    }
}

// ---------------------------------------------------------------------------
// Launcher
// ---------------------------------------------------------------------------
extern "C" void kernel_launch(void* const* d_in, const int* in_sizes, int n_in,
                              void* d_out, int out_size) {
    const float* hs  = (const float*)d_in[0];
    const float* Wq  = (const float*)d_in[1];
    const float* bq  = (const float*)d_in[2];
    const float* Wk  = (const float*)d_in[3];
    const float* bk  = (const float*)d_in[4];
    const float* Wv  = (const float*)d_in[5];
    const float* bv  = (const float*)d_in[6];
    const float* Wo  = (const float*)d_in[7];
    const float* bo  = (const float*)d_in[8];
    const float* rel = (const float*)d_in[9];
    float* out = (float*)d_out;

    cudaFuncSetAttribute(mega, cudaFuncAttributeMaxDynamicSharedMemorySize, MEGA_SMEM);

    prep_kernel<<<8321, 256>>>(hs, Wq, Wk, Wv, Wo, rel);
    mega<<<296, 256, MEGA_SMEM>>>(bq, bk, bv, bo, out);
}

// round 16
// speedup vs baseline: 1.1099x; 1.1099x over previous
#include <cuda_runtime.h>
#include <cuda_fp16.h>
#include <stdint.h>
#include <math.h>

#define BB 2
#define SS 2048
#define EE 1024
#define HH 16
#define DD 64
#define MTOT (BB*SS)

// ---------------------------------------------------------------------------
// Scratch (device globals — no allocation allowed)
// ---------------------------------------------------------------------------
__device__ float g_bias8[HH*SS];                       // bias*8*log2e
__device__ __half g_ahi[MTOT*EE];                      // hs fp16
__device__ __half g_wthi[4u*EE*EE];                    // W^T fp16 (q,k,v,o)
__device__ __half g_chi[MTOT*EE];                      // ctx fp16
__device__ __half g_qhi[BB*HH*SS*DD];                  // [b][h][s][d]
__device__ __half g_khi[BB*HH*SS*DD];                  // [b][h][s][d]
__device__ __half g_vthi[BB*HH*SS*DD];                 // [b][h][d][s]

// scheduling state
__device__ unsigned int g_ctr;
__device__ unsigned int g_flagQ[32*16];   // [mblk][h]
__device__ unsigned int g_cntK[16], g_cntV[16];
__device__ unsigned int g_cntCtx[32];     // [b*16+qt]

#define NQKV 1536
#define NATT 512
#define NOUT 512
#define NTOT (NQKV + NATT + NOUT)

// ---------------------------------------------------------------------------
// helpers
// ---------------------------------------------------------------------------
__device__ __forceinline__ uint32_t smem_u32(const void* p) {
    uint32_t r;
    asm("{ .reg .u64 t; cvta.to.shared.u64 t, %1; cvt.u32.u64 %0, t; }"
        : "=r"(r) : "l"(p));
    return r;
}

__device__ __forceinline__ void cp16(uint32_t dst, const void* src) {
    asm volatile("cp.async.cg.shared.global [%0], [%1], 16;"
                 :: "r"(dst), "l"(__cvta_generic_to_global(src)) : "memory");
}

__device__ __forceinline__ void mma_f16(float* c, const uint32_t* a, const uint32_t* b) {
    asm volatile(
        "mma.sync.aligned.m16n8k16.row.col.f32.f16.f16.f32 "
        "{%0,%1,%2,%3}, {%4,%5,%6,%7}, {%8,%9}, {%0,%1,%2,%3};"
        : "+f"(c[0]), "+f"(c[1]), "+f"(c[2]), "+f"(c[3])
        : "r"(a[0]), "r"(a[1]), "r"(a[2]), "r"(a[3]), "r"(b[0]), "r"(b[1]));
}

__device__ __forceinline__ void ldsm_x4(uint32_t* r, uint32_t addr) {
    asm volatile("ldmatrix.sync.aligned.m8n8.x4.shared.b16 {%0,%1,%2,%3}, [%4];"
        : "=r"(r[0]), "=r"(r[1]), "=r"(r[2]), "=r"(r[3]) : "r"(addr));
}

__device__ __forceinline__ uint32_t pack_f16x2(float a, float b) {
    uint32_t d;
    asm("cvt.rn.f16x2.f32 %0, %1, %2;" : "=r"(d) : "f"(b), "f"(a));
    return d;
}

// ---------------------------------------------------------------------------
// prep kernel: weight transpose + hs convert + bias table + flag zeroing
// ---------------------------------------------------------------------------
__global__ void prep_kernel(const float* __restrict__ hs,
                            const float* __restrict__ Wq, const float* __restrict__ Wk,
                            const float* __restrict__ Wv, const float* __restrict__ Wo,
                            const float* __restrict__ rel_bias) {
    int bx = blockIdx.x, tid = threadIdx.x;
    if (bx < 4096) {
        __shared__ float t[32][33];
        int widx = bx >> 10, tile = bx & 1023;
        const float* W = (widx == 0) ? Wq : (widx == 1) ? Wk : (widx == 2) ? Wv : Wo;
        int n0 = (tile & 31) * 32, k0 = (tile >> 5) * 32;
        int tx = tid & 31, ty = tid >> 5;
#pragma unroll
        for (int i = 0; i < 4; i++)
            t[ty + i * 8][tx] = W[(size_t)(k0 + ty + i * 8) * EE + n0 + tx];
        __syncthreads();
        __half* hi = g_wthi + (size_t)widx * EE * EE;
#pragma unroll
        for (int i = 0; i < 4; i++) {
            int n = n0 + ty + i * 8, k = k0 + tx;
            hi[(size_t)n * EE + k] = __float2half(t[tx][ty + i * 8]);
        }
    } else if (bx < 8192) {
        int i = (bx - 4096) * 256 + tid;
        float4 v = ((const float4*)hs)[i];
        ((uint32_t*)g_ahi)[i * 2]     = pack_f16x2(v.x, v.y);
        ((uint32_t*)g_ahi)[i * 2 + 1] = pack_f16x2(v.z, v.w);
    } else if (bx < 8320) {
        int idx = (bx - 8192) * 256 + tid;
        int h = idx / SS, d = idx % SS;
        int bucket;
        if (d < 16) bucket = d;
        else {
            float t2 = (logf((float)d * 0.0625f) / 1.3862943611198906f) * 16.0f;
            int lb = 16 + (int)t2;
            bucket = lb < 31 ? lb : 31;
        }
        g_bias8[idx] = rel_bias[bucket * HH + h] * (8.0f * 1.4426950408889634f);
    } else {
        if (tid == 0) g_ctr = 0;
        if (tid < 512) g_flagQ[tid] = 0;
        if (tid < 16) { g_cntK[tid] = 0; g_cntV[tid] = 0; }
        if (tid < 32) g_cntCtx[tid] = 0;
    }
}

// ---------------------------------------------------------------------------
// GEMM tile body (BM=128, BN=64, BK=32, 4-stage, 8 warps 4m x 2n)
// ---------------------------------------------------------------------------
#define RPAD 80
#define ATILE (128 * RPAD)
#define BTILE (64 * RPAD)
#define STAGE_BYTES (ATILE + BTILE)
#define NITER 32

__device__ __forceinline__ void gemm_tile(char* sm, const __half* A, const __half* Bw,
                                          const float* bias, float* outp,
                                          int mblk, int nblk, int widx) {
    int tid = threadIdx.x;
    int lane = tid & 31, wid = tid >> 5;
    int wm = wid & 3, wn = wid >> 2;
    int g = lane >> 2, tg = lane & 3;
    int m0 = mblk * 128, n0 = nblk * 64;

    float c[2][4][4];
#pragma unroll
    for (int mt = 0; mt < 2; mt++)
#pragma unroll
        for (int nt = 0; nt < 4; nt++)
#pragma unroll
            for (int i = 0; i < 4; i++) c[mt][nt][i] = 0.f;

    uint32_t smbase = smem_u32(sm);
    uint32_t a_lrow = ((uint32_t)((lane >> 3) & 1)) * 8 + (lane & 7);
    uint32_t a_lcol = ((uint32_t)(lane >> 4)) * 16;
    uint32_t b_lrow = lane & 7;
    uint32_t b_lcol = ((uint32_t)(lane >> 3)) * 16;

    auto load_stage = [&](int git, int s) {
        int kb = git * 32;
        uint32_t st = smbase + s * STAGE_BYTES;
#pragma unroll
        for (int i = 0; i < 2; i++) {
            int ch = tid + i * 256;
            int m = ch >> 2, lk = ch & 3;
            cp16(st + m * RPAD + lk * 16, A + (size_t)(m0 + m) * EE + kb + lk * 8);
        }
        {
            int mb = tid >> 2, lkb = tid & 3;
            cp16(st + ATILE + mb * RPAD + lkb * 16,
                 Bw + (size_t)(n0 + mb) * EE + kb + lkb * 8);
        }
    };

#pragma unroll
    for (int p = 0; p < 3; p++) {
        load_stage(p, p);
        asm volatile("cp.async.commit_group;" ::: "memory");
    }

    for (int git = 0; git < NITER; git++) {
        asm volatile("cp.async.wait_group 2;" ::: "memory");
        __syncthreads();

        int nx = git + 3;
        if (nx < NITER) load_stage(nx, nx & 3);
        asm volatile("cp.async.commit_group;" ::: "memory");

        uint32_t st = smbase + (git & 3) * STAGE_BYTES;
        uint32_t Bs = st + ATILE;

        uint32_t b[4][4];
#pragma unroll
        for (int nt = 0; nt < 4; nt++)
            ldsm_x4(b[nt], Bs + (wn * 32 + nt * 8 + b_lrow) * RPAD + b_lcol);

        uint32_t a[2][8];
#pragma unroll
        for (int mt = 0; mt < 2; mt++)
#pragma unroll
            for (int ks = 0; ks < 2; ks++)
                ldsm_x4(&a[mt][ks * 4],
                        st + (wm * 32 + mt * 16 + a_lrow) * RPAD + ks * 32 + a_lcol);
#pragma unroll
        for (int ks = 0; ks < 2; ks++)
#pragma unroll
            for (int mt = 0; mt < 2; mt++)
#pragma unroll
                for (int nt = 0; nt < 4; nt++)
                    mma_f16(c[mt][nt], &a[mt][ks * 4], &b[nt][ks * 2]);
    }

    // epilogue
#pragma unroll
    for (int mt = 0; mt < 2; mt++) {
#pragma unroll
        for (int nt = 0; nt < 4; nt++) {
            int n = n0 + wn * 32 + nt * 8 + 2 * tg;
            float bx = bias[n], by = bias[n + 1];
#pragma unroll
            for (int hh = 0; hh < 2; hh++) {
                int r = m0 + wm * 32 + mt * 16 + g + hh * 8;
                float vx = c[mt][nt][2 * hh] + bx;
                float vy = c[mt][nt][2 * hh + 1] + by;
                if (widx == 3) {
                    *(float2*)(outp + (size_t)r * EE + n) = make_float2(vx, vy);
                } else {
                    uint32_t hp = pack_f16x2(vx, vy);
                    int head = n >> 6, d = n & 63;
                    int bidx = r >> 11, srow = r & 2047;
                    size_t bh = (size_t)bidx * HH + head;
                    if (widx == 2) {
                        size_t i0 = (bh * DD + d) * SS + srow;
                        size_t i1 = (bh * DD + d + 1) * SS + srow;
                        g_vthi[i0] = __ushort_as_half((unsigned short)(hp & 0xffff));
                        g_vthi[i1] = __ushort_as_half((unsigned short)(hp >> 16));
                    } else if (widx == 1) {
                        *(uint32_t*)(g_khi + (bh * SS + srow) * DD + d) = hp;
                    } else {
                        *(uint32_t*)(g_qhi + (bh * SS + srow) * DD + d) = hp;
                    }
                }
            }
        }
    }

    if (widx != 3) {
        __threadfence();
        __syncthreads();
        if (tid == 0) {
            if (widx == 0)      atomicExch(&g_flagQ[mblk * 16 + nblk], 1u);
            else if (widx == 1) atomicAdd(&g_cntK[nblk], 1u);
            else                atomicAdd(&g_cntV[nblk], 1u);
        }
    }
}

// ---------------------------------------------------------------------------
// attention tile body: fixed-max softmax (M=12, exp2 domain)
// ---------------------------------------------------------------------------
#define QT 128
#define KT 64
#define PITCH 144
#define KV_TILE (KT * PITCH)
#define KV_STAGE (2 * KV_TILE)
#define OFF_Q  8192
#define OFF_ST (OFF_Q + QT * PITCH)
#define MEGA_SMEM (OFF_ST + 3 * KV_STAGE)   // 81920

#define SCALE_L2E 0.18033688011112042f      // 0.125 * log2(e)
#define FIXMAX 12.0f

__device__ __forceinline__ void attn_tile(char* sm, int qt, int h, int b) {
    float* bias_s = (float*)sm;
    uint32_t smb = smem_u32(sm);
    int tid = threadIdx.x, lane = tid & 31, w = tid >> 5;
    int g = lane >> 2, tg = lane & 3;
    int q0 = qt * QT;
    size_t bh = (size_t)b * HH + h;
    int mblk = b * 16 + qt;

    // wait for producers
    if (tid == 0) {
        while (atomicAdd(&g_flagQ[mblk * 16 + h], 0u) == 0u) __nanosleep(64);
        while (atomicAdd(&g_cntK[h], 0u) < 32u) __nanosleep(64);
        while (atomicAdd(&g_cntV[h], 0u) < 32u) __nanosleep(64);
        __threadfence();
    }
    __syncthreads();

    const __half* Khi = g_khi + bh * SS * DD;
    const __half* Vhi = g_vthi + bh * DD * SS;
    const __half* Qhi = g_qhi + (bh * SS + q0) * DD;

    const float4* br = (const float4*)(g_bias8 + h * SS);
    for (int i = tid; i < SS / 4; i += 256) ((float4*)bias_s)[i] = br[i];

    auto load_kv = [&](int kt, int s) {
        uint32_t base = smb + OFF_ST + s * KV_STAGE;
        int k0 = kt * KT;
#pragma unroll
        for (int i = 0; i < 2; i++) {
            int ch = tid + i * 256;
            int r = ch >> 3, cc = ch & 7;
            uint32_t off = r * PITCH + cc * 16;
            cp16(base + off,           Khi + (size_t)(k0 + r) * 64 + cc * 8);
            cp16(base + KV_TILE + off, Vhi + (size_t)r * SS + k0 + cc * 8);
        }
    };

#pragma unroll
    for (int i = 0; i < 4; i++) {
        int ch = tid + i * 256;
        int r = ch >> 3, cc = ch & 7;
        cp16(smb + OFF_Q + r * PITCH + cc * 16, Qhi + r * 64 + cc * 8);
    }
    load_kv(0, 0);
    asm volatile("cp.async.commit_group;" ::: "memory");
    load_kv(1, 1);
    asm volatile("cp.async.commit_group;" ::: "memory");

    float l0 = 0.f, l1 = 0.f;
    float acc[8][4];
#pragma unroll
    for (int j = 0; j < 8; j++)
#pragma unroll
        for (int i = 0; i < 4; i++) acc[j][i] = 0.f;

    uint32_t qh[16];
    int qrow0 = q0 + w * 16 + g;
    int qrow1 = qrow0 + 8;

    uint32_t a_lrow = ((uint32_t)((lane >> 3) & 1)) * 8 + (lane & 7);
    uint32_t a_lcol = ((uint32_t)(lane >> 4)) * 16;
    uint32_t kv_off = (lane & 7) * PITCH + ((uint32_t)(lane >> 3)) * 16;

    for (int kt = 0; kt < 32; kt++) {
        asm volatile("cp.async.wait_group 1;" ::: "memory");
        __syncthreads();

        if (kt + 2 < 32) load_kv(kt + 2, (kt + 2) % 3);
        asm volatile("cp.async.commit_group;" ::: "memory");

        if (kt == 0) {
#pragma unroll
            for (int s = 0; s < 4; s++)
                ldsm_x4(&qh[4 * s],
                        smb + OFF_Q + (w * 16 + a_lrow) * PITCH + s * 32 + a_lcol);
        }

        uint32_t stg = smb + OFF_ST + (kt % 3) * KV_STAGE;

        // ---- S = Q K^T ----
        float sc[8][4];
#pragma unroll
        for (int j = 0; j < 8; j++) {
#pragma unroll
            for (int i = 0; i < 4; i++) sc[j][i] = 0.f;
            uint32_t kbase = stg + j * (8 * PITCH) + kv_off;
            uint32_t kh[8];
            ldsm_x4(&kh[0], kbase);
            ldsm_x4(&kh[4], kbase + 64);
#pragma unroll
            for (int s = 0; s < 4; s++)
                mma_f16(sc[j], &qh[4 * s], &kh[2 * s]);
        }

        // ---- p = exp2(scale*S + bias - FIXMAX); accumulate l ----
        int colb = kt * KT + 2 * tg;
#pragma unroll
        for (int j = 0; j < 8; j++) {
            int col = colb + 8 * j;
            int d0 = qrow0 - col, d1 = qrow1 - col;
            sc[j][0] = exp2f(sc[j][0] * SCALE_L2E + (bias_s[max(d0, 0)] - FIXMAX));
            sc[j][1] = exp2f(sc[j][1] * SCALE_L2E + (bias_s[max(d0 - 1, 0)] - FIXMAX));
            sc[j][2] = exp2f(sc[j][2] * SCALE_L2E + (bias_s[max(d1, 0)] - FIXMAX));
            sc[j][3] = exp2f(sc[j][3] * SCALE_L2E + (bias_s[max(d1 - 1, 0)] - FIXMAX));
            l0 += sc[j][0] + sc[j][1];
            l1 += sc[j][2] + sc[j][3];
        }

        // ---- P -> fp16 fragments ----
        uint32_t ph[8], ph2[8];
#pragma unroll
        for (int j = 0; j < 8; j++) {
            ph[j]  = pack_f16x2(sc[j][0], sc[j][1]);
            ph2[j] = pack_f16x2(sc[j][2], sc[j][3]);
        }

        // ---- O += P V ----
#pragma unroll
        for (int j = 0; j < 8; j++) {
            uint32_t vbase = stg + KV_TILE + j * (8 * PITCH) + kv_off;
            uint32_t vh[8];
            ldsm_x4(&vh[0], vbase);
            ldsm_x4(&vh[4], vbase + 64);
#pragma unroll
            for (int s = 0; s < 4; s++) {
                uint32_t pA[4] = { ph[2*s], ph2[2*s], ph[2*s+1], ph2[2*s+1] };
                mma_f16(acc[j], pA, &vh[2 * s]);
            }
        }
    }

    // ---- final l reduction ----
    l0 += __shfl_xor_sync(0xffffffffu, l0, 1);
    l0 += __shfl_xor_sync(0xffffffffu, l0, 2);
    l1 += __shfl_xor_sync(0xffffffffu, l1, 1);
    l1 += __shfl_xor_sync(0xffffffffu, l1, 2);

    float inv0 = 1.f / l0, inv1 = 1.f / l1;
#pragma unroll
    for (int j = 0; j < 8; j++) {
        int e = h * 64 + 8 * j + 2 * tg;
        {
            float ox = acc[j][0] * inv0, oy = acc[j][1] * inv0;
            size_t base = ((size_t)b * SS + qrow0) * EE + e;
            *(uint32_t*)(g_chi + base) = pack_f16x2(ox, oy);
        }
        {
            float ox = acc[j][2] * inv1, oy = acc[j][3] * inv1;
            size_t base = ((size_t)b * SS + qrow1) * EE + e;
            *(uint32_t*)(g_chi + base) = pack_f16x2(ox, oy);
        }
    }

    __threadfence();
    __syncthreads();
    if (tid == 0) atomicAdd(&g_cntCtx[mblk], 1u);
}

// ---------------------------------------------------------------------------
// mega kernel: persistent CTAs, dynamic tile claiming
//   tiles [0,512):     K tiles   (h = t>>5,  mblk = t&31)
//   tiles [512,1024):  V tiles   (h = t'>>5, mblk = t'&31)
//   tiles [1024,1536): Q tiles   (mblk = t'>>4, h = t'&15)  == attention order
//   tiles [1536,2048): attention (bqt = t2>>4, h = t2&15)
//   tiles [2048,2560): O-proj    (bulk ctx wait)
// ---------------------------------------------------------------------------
__global__ __launch_bounds__(256, 2)
void mega(const float* __restrict__ bq, const float* __restrict__ bk,
          const float* __restrict__ bv, const float* __restrict__ bo,
          float* __restrict__ outp) {
    extern __shared__ char sm[];
    __shared__ unsigned int s_t;

    for (;;) {
        if (threadIdx.x == 0) s_t = atomicAdd(&g_ctr, 1u);
        __syncthreads();
        unsigned int t = s_t;
        if (t >= NTOT) return;

        if (t < 512) {
            // K projection
            int h = t >> 5, mblk = t & 31;
            gemm_tile(sm, g_ahi, g_wthi + (size_t)1 * EE * EE, bk, nullptr, mblk, h, 1);
        } else if (t < 1024) {
            // V projection
            int t1 = t - 512;
            int h = t1 >> 5, mblk = t1 & 31;
            gemm_tile(sm, g_ahi, g_wthi + (size_t)2 * EE * EE, bv, nullptr, mblk, h, 2);
        } else if (t < 1536) {
            // Q projection, ordered to match attention consumption
            int t1 = t - 1024;
            int mblk = t1 >> 4, h = t1 & 15;
            gemm_tile(sm, g_ahi, g_wthi, bq, nullptr, mblk, h, 0);
        } else if (t < NQKV + NATT) {
            int t2 = t - NQKV;
            int bqt = t2 >> 4, h = t2 & 15;
            attn_tile(sm, bqt & 15, h, bqt >> 4);
        } else {
            int t3 = t - NQKV - NATT;
            int mblk = t3 >> 4, nblk = t3 & 15;
            if (threadIdx.x == 0) {
                while (atomicAdd(&g_cntCtx[mblk], 0u) < 16u) __nanosleep(64);
                __threadfence();
            }
            __syncthreads();
            gemm_tile(sm, g_chi, g_wthi + (size_t)3 * EE * EE, bo, outp, mblk, nblk, 3);
        }
        __syncthreads();
    }
}

// ---------------------------------------------------------------------------
// Launcher
// ---------------------------------------------------------------------------
extern "C" void kernel_launch(void* const* d_in, const int* in_sizes, int n_in,
                              void* d_out, int out_size) {
    const float* hs  = (const float*)d_in[0];
    const float* Wq  = (const float*)d_in[1];
    const float* bq  = (const float*)d_in[2];
    const float* Wk  = (const float*)d_in[3];
    const float* bk  = (const float*)d_in[4];
    const float* Wv  = (const float*)d_in[5];
    const float* bv  = (const float*)d_in[6];
    const float* Wo  = (const float*)d_in[7];
    const float* bo  = (const float*)d_in[8];
    const float* rel = (const float*)d_in[9];
    float* out = (float*)d_out;

    cudaFuncSetAttribute(mega, cudaFuncAttributeMaxDynamicSharedMemorySize, MEGA_SMEM);

    prep_kernel<<<8321, 256>>>(hs, Wq, Wk, Wv, Wo, rel);
    mega<<<296, 256, MEGA_SMEM>>>(bq, bk, bv, bo, out);
}